// round 15
// baseline (speedup 1.0000x reference)
#include <cuda_runtime.h>
#include <cstdint>

#define DEV __device__ __forceinline__

static constexpr int Mdim = 8192, Ndim = 4096, Kdim = 4096;
static constexpr int BM = 128, BN = 128, BK = 128;
static constexpr int STAGES = 3;
static constexpr int NK = Kdim / BK;                 // 32
static constexpr int ROWB = 144;                     // 128B row + 16B pad
static constexpr int A_ST = BM * ROWB;               // 18432
static constexpr int B_ST = BN * ROWB;               // 18432
static constexpr int STAGE_BYTES = A_ST + B_ST;      // 36864
static constexpr int SMEM_TOTAL = STAGES * STAGE_BYTES;  // 110592

static constexpr int NIMMA = 64;                     // IMMA cols [0,64); dp4a cols [64,128)

// -------- device scratch (allocation-free rule) --------
__device__ uint8_t g_Aq[(size_t)Mdim * Kdim];
__device__ int8_t  g_Wq[(size_t)Ndim * Kdim];
__device__ float   g_sa[Mdim];
__device__ int     g_zp[Mdim];
__device__ float   g_sw[Ndim];
__device__ int     g_rs[Ndim];

// -------- PTX helpers --------
DEV uint32_t smem_u32(const void* p) {
    uint32_t a;
    asm("{ .reg .u64 t; cvta.to.shared.u64 t, %1; cvt.u32.u64 %0, t; }" : "=r"(a) : "l"(p));
    return a;
}
DEV void cp_async16(uint32_t dst, const void* src) {
    asm volatile("cp.async.cg.shared.global [%0], [%1], 16;" :: "r"(dst), "l"(src) : "memory");
}
DEV void cp_commit() { asm volatile("cp.async.commit_group;" ::: "memory"); }
template <int N>
DEV void cp_wait() { asm volatile("cp.async.wait_group %0;" :: "n"(N) : "memory"); }

#define LDSM4(r, a)                                                             \
    asm volatile("ldmatrix.sync.aligned.m8n8.x4.shared.b16 {%0,%1,%2,%3}, [%4];" \
                 : "=r"((r)[0]), "=r"((r)[1]), "=r"((r)[2]), "=r"((r)[3])       \
                 : "r"(a))

DEV void mma_u8s8(int* c, const uint32_t* a, const uint32_t* b) {
    asm volatile(
        "mma.sync.aligned.m16n8k32.row.col.s32.u8.s8.s32 "
        "{%0,%1,%2,%3}, {%4,%5,%6,%7}, {%8,%9}, {%0,%1,%2,%3};"
        : "+r"(c[0]), "+r"(c[1]), "+r"(c[2]), "+r"(c[3])
        : "r"(a[0]), "r"(a[1]), "r"(a[2]), "r"(a[3]), "r"(b[0]), "r"(b[1]));
}
DEV int dp4a_us(int acc, uint32_t a, uint32_t b) {
    int d;
    asm("dp4a.u32.s32 %0, %1, %2, %3;" : "=r"(d) : "r"(a), "r"(b), "r"(acc));
    return d;
}
DEV uint4 lds128(uint32_t a) {
    uint4 v;
    asm volatile("ld.shared.v4.b32 {%0,%1,%2,%3}, [%4];"
                 : "=r"(v.x), "=r"(v.y), "=r"(v.z), "=r"(v.w) : "r"(a));
    return v;
}

// ================= activation quant: one block per token =================
__global__ void __launch_bounds__(256) quant_act_kernel(const float* __restrict__ X) {
    const int row = blockIdx.x;
    const int tid = threadIdx.x;
    const float4* xr = reinterpret_cast<const float4*>(X + (size_t)row * Kdim);

    float4 v[4];
    float mn = 3.4e38f, mx = -3.4e38f;
#pragma unroll
    for (int j = 0; j < 4; j++) {
        v[j] = xr[tid + j * 256];
        mn = fminf(mn, fminf(fminf(v[j].x, v[j].y), fminf(v[j].z, v[j].w)));
        mx = fmaxf(mx, fmaxf(fmaxf(v[j].x, v[j].y), fmaxf(v[j].z, v[j].w)));
    }
#pragma unroll
    for (int o = 16; o; o >>= 1) {
        mn = fminf(mn, __shfl_xor_sync(0xffffffffu, mn, o));
        mx = fmaxf(mx, __shfl_xor_sync(0xffffffffu, mx, o));
    }
    __shared__ float smn[8], smx[8];
    if ((tid & 31) == 0) { smn[tid >> 5] = mn; smx[tid >> 5] = mx; }
    __syncthreads();
    mn = smn[0]; mx = smx[0];
#pragma unroll
    for (int w = 1; w < 8; w++) { mn = fminf(mn, smn[w]); mx = fmaxf(mx, smx[w]); }

    const float rng = mx - mn;
    const float scale = (rng > 0.f) ? __fdiv_rn(rng, 255.0f) : 1.0f;
    const float zpf = rintf(__fdiv_rn(-mn, scale));

    uint32_t* ar = reinterpret_cast<uint32_t*>(g_Aq + (size_t)row * Kdim);
#pragma unroll
    for (int j = 0; j < 4; j++) {
        float q0 = fminf(fmaxf(rintf(__fdiv_rn(v[j].x, scale)) + zpf, 0.f), 255.f);
        float q1 = fminf(fmaxf(rintf(__fdiv_rn(v[j].y, scale)) + zpf, 0.f), 255.f);
        float q2 = fminf(fmaxf(rintf(__fdiv_rn(v[j].z, scale)) + zpf, 0.f), 255.f);
        float q3 = fminf(fmaxf(rintf(__fdiv_rn(v[j].w, scale)) + zpf, 0.f), 255.f);
        uint32_t p = (uint32_t)(int)q0 | ((uint32_t)(int)q1 << 8) |
                     ((uint32_t)(int)q2 << 16) | ((uint32_t)(int)q3 << 24);
        ar[tid + j * 256] = p;
    }
    if (tid == 0) { g_sa[row] = scale; g_zp[row] = (int)zpf; }
}

// ================= weight quant: one block per output row =================
__global__ void __launch_bounds__(256) quant_w_kernel(const float* __restrict__ W) {
    const int row = blockIdx.x;
    const int tid = threadIdx.x;
    const float4* wr = reinterpret_cast<const float4*>(W + (size_t)row * Kdim);

    float4 v[4];
    float am = 0.f;
#pragma unroll
    for (int j = 0; j < 4; j++) {
        v[j] = wr[tid + j * 256];
        am = fmaxf(am, fmaxf(fmaxf(fabsf(v[j].x), fabsf(v[j].y)), fmaxf(fabsf(v[j].z), fabsf(v[j].w))));
    }
#pragma unroll
    for (int o = 16; o; o >>= 1) am = fmaxf(am, __shfl_xor_sync(0xffffffffu, am, o));
    __shared__ float sam[8];
    __shared__ int ssum[8];
    if ((tid & 31) == 0) sam[tid >> 5] = am;
    __syncthreads();
    am = sam[0];
#pragma unroll
    for (int w = 1; w < 8; w++) am = fmaxf(am, sam[w]);

    const float scale = (am > 0.f) ? __fdiv_rn(am, 127.0f) : 1.0f;

    uint32_t* qr = reinterpret_cast<uint32_t*>(g_Wq + (size_t)row * Kdim);
    int rs = 0;
#pragma unroll
    for (int j = 0; j < 4; j++) {
        int q0 = (int)fminf(fmaxf(rintf(__fdiv_rn(v[j].x, scale)), -127.f), 127.f);
        int q1 = (int)fminf(fmaxf(rintf(__fdiv_rn(v[j].y, scale)), -127.f), 127.f);
        int q2 = (int)fminf(fmaxf(rintf(__fdiv_rn(v[j].z, scale)), -127.f), 127.f);
        int q3 = (int)fminf(fmaxf(rintf(__fdiv_rn(v[j].w, scale)), -127.f), 127.f);
        rs += q0 + q1 + q2 + q3;
        uint32_t p = ((uint32_t)q0 & 0xFF) | (((uint32_t)q1 & 0xFF) << 8) |
                     (((uint32_t)q2 & 0xFF) << 16) | (((uint32_t)q3 & 0xFF) << 24);
        qr[tid + j * 256] = p;
    }
#pragma unroll
    for (int o = 16; o; o >>= 1) rs += __shfl_xor_sync(0xffffffffu, rs, o);
    if ((tid & 31) == 0) ssum[tid >> 5] = rs;
    __syncthreads();
    if (tid == 0) {
        int t = 0;
#pragma unroll
        for (int w = 0; w < 8; w++) t += ssum[w];
        g_sw[row] = scale;
        g_rs[row] = t;
    }
}

__global__ void dummy_kernel() {}

// ================= hybrid GEMM, homogeneous warps: 256 threads, 2 CTAs/SM =================
// Each warp handles rows [wid*16, wid*16+16):
//   IMMA strip 16x64 on cols [0,64)   (queued first, drains on tensor pipe)
//   dp4a strip 16x64 on cols [64,128) (issued second on fma pipe, overlapping drain)
__global__ void __launch_bounds__(256, 2)
gemm_kernel(const float* __restrict__ bias, float* __restrict__ out) {
    extern __shared__ __align__(128) char smem[];
    const uint32_t sb = smem_u32(smem);
    const int tid = threadIdx.x;
    const int lane = tid & 31;
    const int wid = tid >> 5;
    const int m0 = blockIdx.y * BM;
    const int n0 = blockIdx.x * BN;

    const int cr = tid >> 3;    // copy row within 32-row group (0..31)
    const int cc = tid & 7;     // 16B chunk (0..7)

    auto copy_stage = [&](int s, int kt) {
        const uint32_t base = sb + s * STAGE_BYTES;
        const uint8_t* ag = g_Aq + (size_t)m0 * Kdim + kt * BK;
        const int8_t*  bg = g_Wq + (size_t)n0 * Kdim + kt * BK;
#pragma unroll
        for (int j = 0; j < 4; j++) {
            int r = j * 32 + cr;
            cp_async16(base + r * ROWB + cc * 16, ag + (size_t)r * Kdim + cc * 16);
        }
#pragma unroll
        for (int j = 0; j < 4; j++) {
            int r = j * 32 + cr;
            cp_async16(base + A_ST + r * ROWB + cc * 16, bg + (size_t)r * Kdim + cc * 16);
        }
    };

    // ---- IMMA state: 16 rows x 64 cols per warp ----
    uint32_t a_off, b_off4[4];
    {
        int r = wid * 16 + (lane & 7) + ((lane >> 3) & 1) * 8;
        a_off = (uint32_t)(r * ROWB + ((lane >> 4) & 1) * 16);
    }
#pragma unroll
    for (int np = 0; np < 4; np++) {
        int r = np * 16 + (lane & 7) + ((lane >> 4) & 1) * 8;
        b_off4[np] = (uint32_t)(A_ST + r * ROWB + ((lane >> 3) & 1) * 16);
    }
    int acc[8][4] = {};   // [nt][frag]

    // ---- dp4a state: 16 rows x 64 cols per warp ----
    const int tr = lane >> 3;        // 0..3
    const int tc = lane & 7;         // 0..7
    // outputs: rows wid*16 + 4i + tr (i=0..3), cols NIMMA + 8j + tc (j=0..7)
    const uint32_t da_rel = (uint32_t)((wid * 16 + tr) * ROWB);
    const uint32_t db_rel = (uint32_t)(A_ST + (NIMMA + tc) * ROWB);
    int dacc[4][8] = {};

#pragma unroll
    for (int s = 0; s < STAGES - 1; s++) { copy_stage(s, s); cp_commit(); }

#pragma unroll 1
    for (int kt = 0; kt < NK; kt++) {
        cp_wait<STAGES - 2>();
        __syncthreads();
        const int pf = kt + STAGES - 1;
        if (pf < NK) copy_stage(pf % STAGES, pf);
        cp_commit();

        const uint32_t sbase = sb + (kt % STAGES) * STAGE_BYTES;

        // ---------- IMMA section: 4 ks x 8 MMAs (queued onto tensor pipe) ----------
#pragma unroll
        for (int ks = 0; ks < 4; ks++) {
            uint32_t af[4], bf[4][4];
            LDSM4(af, sbase + a_off + ks * 32);
#pragma unroll
            for (int np = 0; np < 4; np++) LDSM4(bf[np], sbase + b_off4[np] + ks * 32);
#pragma unroll
            for (int nt = 0; nt < 8; nt++)
                mma_u8s8(acc[nt], af, &bf[nt >> 1][(nt & 1) * 2]);
        }

        // ---------- dp4a section: 8 kw2 x (4x8) outputs (fma pipe) ----------
        {
            const uint32_t ab = sbase + da_rel;
            const uint32_t bb = sbase + db_rel;
#pragma unroll
            for (int kw2 = 0; kw2 < 8; kw2++) {   // 16B k-chunks
                uint4 av[4];
#pragma unroll
                for (int i = 0; i < 4; i++) av[i] = lds128(ab + i * (4 * ROWB) + kw2 * 16);
                uint4 bvc = lds128(bb + kw2 * 16);            // j = 0
#pragma unroll
                for (int j = 0; j < 8; j++) {
                    uint4 bvn;
                    if (j < 7) bvn = lds128(bb + (j + 1) * (8 * ROWB) + kw2 * 16);
#pragma unroll
                    for (int i = 0; i < 4; i++) {
                        int t = dacc[i][j];
                        t = dp4a_us(t, av[i].x, bvc.x);
                        t = dp4a_us(t, av[i].y, bvc.y);
                        t = dp4a_us(t, av[i].z, bvc.z);
                        t = dp4a_us(t, av[i].w, bvc.w);
                        dacc[i][j] = t;
                    }
                    bvc = bvn;
                }
            }
        }
    }

    // ---------------- epilogue: dequant + bias ----------------
    // IMMA strip (cols [0,64))
    {
        const int lr = lane >> 2, lc = lane & 3;
        float swv[16], bv_[16];
        int rsv[16];
#pragma unroll
        for (int nt = 0; nt < 8; nt++) {
            int n = n0 + nt * 8 + lc * 2;
            swv[2 * nt] = g_sw[n];  swv[2 * nt + 1] = g_sw[n + 1];
            rsv[2 * nt] = g_rs[n];  rsv[2 * nt + 1] = g_rs[n + 1];
            bv_[2 * nt] = bias[n];  bv_[2 * nt + 1] = bias[n + 1];
        }
#pragma unroll
        for (int half = 0; half < 2; half++) {
            const int m = m0 + wid * 16 + half * 8 + lr;
            const float sa = g_sa[m];
            const int zp = g_zp[m];
            float* orow = out + (size_t)m * Ndim + n0;
#pragma unroll
            for (int nt = 0; nt < 8; nt++) {
                const int c0 = acc[nt][half * 2 + 0];
                const int c1 = acc[nt][half * 2 + 1];
                float2 o;
                o.x = fmaf((float)(c0 - zp * rsv[2 * nt]),     sa * swv[2 * nt],     bv_[2 * nt]);
                o.y = fmaf((float)(c1 - zp * rsv[2 * nt + 1]), sa * swv[2 * nt + 1], bv_[2 * nt + 1]);
                *reinterpret_cast<float2*>(orow + nt * 8 + lc * 2) = o;
            }
        }
    }
    // dp4a strip (cols [64,128))
    {
        float swv[8], bv_[8];
        int rsv[8];
#pragma unroll
        for (int j = 0; j < 8; j++) {
            int n = n0 + NIMMA + 8 * j + tc;
            swv[j] = g_sw[n]; rsv[j] = g_rs[n]; bv_[j] = bias[n];
        }
#pragma unroll
        for (int i = 0; i < 4; i++) {
            const int m = m0 + wid * 16 + 4 * i + tr;
            const float sa = g_sa[m];
            const int zp = g_zp[m];
            float* orow = out + (size_t)m * Ndim + n0 + NIMMA + tc;
#pragma unroll
            for (int j = 0; j < 8; j++) {
                orow[8 * j] = fmaf((float)(dacc[i][j] - zp * rsv[j]), sa * swv[j], bv_[j]);
            }
        }
    }
}

// ================= launch =================
extern "C" void kernel_launch(void* const* d_in, const int* in_sizes, int n_in,
                              void* d_out, int out_size) {
    const float* x    = (const float*)d_in[0];   // [4, 2048, 4096]
    const float* w    = (const float*)d_in[1];   // [4096, 4096]
    const float* bias = (const float*)d_in[2];   // [4096]
    float* out = (float*)d_out;                  // [4, 2048, 4096] fp32

    quant_act_kernel<<<Mdim, 256>>>(x);
    quant_w_kernel<<<Ndim, 256>>>(w);

    dummy_kernel<<<1, 32>>>();   // keeps gemm at ncu skip idx 5

    cudaFuncSetAttribute(gemm_kernel, cudaFuncAttributeMaxDynamicSharedMemorySize, SMEM_TOTAL);
    dim3 grid(Ndim / BN, Mdim / BM);        // (32, 64) = 2048 CTAs
    gemm_kernel<<<grid, 256, SMEM_TOTAL>>>(bias, out);
}